// round 2
// baseline (speedup 1.0000x reference)
#include <cuda_runtime.h>
#include <math.h>

#define NDIM 512
#define DDIM 784
#define BDIM 128
#define CDIM 10
#define ITERS 40
#define QMAX 127.0f

#define MT 8          // row tiles (64 rows each)
#define NT 16         // column groups (8 cols each)
#define NBLK 8
#define MROWS 64
#define GRID (MT*NT)  // 128 CTAs
#define TPB 256
#define WSTRIDE 68    // padded k-row stride for sWt (bank-friendly, 16B aligned)

#define SMEM_FLOATS (34816 + 4096 + 2048 + 512)
#define SMEM_BYTES  (SMEM_FLOATS * 4)

// ---- device globals (scratch; no allocation at runtime) ----
__device__ float g_Ux[NDIM*BDIM];     // blocked: [group][n][8]
__device__ float g_zA[NDIM*BDIM];
__device__ float g_zB[NDIM*BDIM];
__device__ unsigned g_maxW, g_maxU, g_maxB;
__device__ unsigned g_gcnt, g_ggen;          // full-grid barrier
__device__ unsigned g_cnt[NT], g_gen[NT];    // per-group barriers

__device__ __forceinline__ void sysbar(volatile unsigned* cnt, volatile unsigned* gen,
                                       unsigned expected) {
    __syncthreads();
    if (threadIdx.x == 0) {
        unsigned snap = *gen;
        __threadfence();
        unsigned t = atomicAdd((unsigned*)cnt, 1u);
        if (t == expected - 1u) {
            *cnt = 0u;
            __threadfence();
            atomicAdd((unsigned*)gen, 1u);
        } else {
            while (*gen == snap) { __nanosleep(64); }
        }
        __threadfence();
    }
    __syncthreads();
}

__device__ __forceinline__ float warpmax(float v) {
    #pragma unroll
    for (int o = 16; o; o >>= 1) v = fmaxf(v, __shfl_xor_sync(0xffffffffu, v, o));
    return v;
}

extern "C" __global__ void __launch_bounds__(TPB, 1)
mondeq_kernel(const float* __restrict__ W, const float* __restrict__ U,
              const float* __restrict__ bvec, const float* __restrict__ x,
              const float* __restrict__ Wc, const float* __restrict__ bcv,
              float* __restrict__ out)
{
    extern __shared__ float sm[];
    const int tid = threadIdx.x;
    const int cta = blockIdx.x;
    const int mi  = cta & (MT - 1);   // row tile
    const int nj  = cta >> 3;         // column group

    // ================= Phase A: per-tensor max|.| =================
    {
        float lw = 0.f, lu = 0.f, lb = 0.f;
        const int gid = cta * TPB + tid;
        for (int i = gid; i < NDIM*NDIM; i += GRID*TPB) lw = fmaxf(lw, fabsf(W[i]));
        for (int i = gid; i < NDIM*DDIM; i += GRID*TPB) lu = fmaxf(lu, fabsf(U[i]));
        if (gid < NDIM) lb = fabsf(bvec[gid]);
        lw = warpmax(lw); lu = warpmax(lu); lb = warpmax(lb);
        const int wid = tid >> 5, lane = tid & 31;
        if (lane == 0) { sm[wid] = lw; sm[8 + wid] = lu; sm[16 + wid] = lb; }
        __syncthreads();
        if (tid == 0) {
            float mw = 0.f, mu = 0.f, mb = 0.f;
            #pragma unroll
            for (int i = 0; i < 8; ++i) {
                mw = fmaxf(mw, sm[i]); mu = fmaxf(mu, sm[8+i]); mb = fmaxf(mb, sm[16+i]);
            }
            atomicMax(&g_maxW, __float_as_uint(mw));
            atomicMax(&g_maxU, __float_as_uint(mu));
            atomicMax(&g_maxB, __float_as_uint(mb));
        }
    }
    sysbar(&g_gcnt, &g_ggen, GRID);

    const float scW = __uint_as_float(*(volatile unsigned*)&g_maxW) / QMAX;
    const float scU = __uint_as_float(*(volatile unsigned*)&g_maxU) / QMAX;
    const float scB = __uint_as_float(*(volatile unsigned*)&g_maxB) / QMAX;

    // ================= Phase B: Ux = Uq @ x^T + bq  (4 rows per CTA) =================
    {
        float* xs = sm;            // 128 x 112, stride 113 (conflict-free reads)
        float* us = sm + 14464;    // 4 x 112 quantized U rows
        float* hb = sm + 14912;    // 512 half-combine scratch
        const int n0   = cta * 4;
        const int half = tid >> 7;
        const int bcol = tid & 127;
        float a0 = 0.f, a1 = 0.f, a2 = 0.f, a3 = 0.f;
        for (int ch = 0; ch < 7; ++ch) {
            const int k0 = ch * 112;
            __syncthreads();
            for (int i = tid; i < 128*112; i += TPB) {
                int bb = i / 112, kk = i - bb*112;
                xs[bb*113 + kk] = x[bb*DDIM + k0 + kk];
            }
            for (int i = tid; i < 4*112; i += TPB) {
                int rr = i / 112, kk = i - rr*112;
                us[rr*112 + kk] = rintf(U[(n0+rr)*DDIM + k0 + kk] / scU) * scU;
            }
            __syncthreads();
            if ((ch & 1) == half) {
                const float* xr = xs + bcol*113;
                #pragma unroll 4
                for (int kk = 0; kk < 112; ++kk) {
                    float xv = xr[kk];
                    a0 = fmaf(us[kk],       xv, a0);
                    a1 = fmaf(us[112 + kk], xv, a1);
                    a2 = fmaf(us[224 + kk], xv, a2);
                    a3 = fmaf(us[336 + kk], xv, a3);
                }
            }
        }
        __syncthreads();
        if (half == 1) {
            hb[bcol] = a0; hb[128+bcol] = a1; hb[256+bcol] = a2; hb[384+bcol] = a3;
        }
        __syncthreads();
        if (half == 0) {
            const float bq0 = rintf(bvec[n0+0] / scB) * scB;
            const float bq1 = rintf(bvec[n0+1] / scB) * scB;
            const float bq2 = rintf(bvec[n0+2] / scB) * scB;
            const float bq3 = rintf(bvec[n0+3] / scB) * scB;
            const int base = (bcol >> 3) * (NDIM*NBLK) + (bcol & 7);
            g_Ux[base + (n0+0)*8] = a0 + hb[bcol]       + bq0;
            g_Ux[base + (n0+1)*8] = a1 + hb[128 + bcol] + bq1;
            g_Ux[base + (n0+2)*8] = a2 + hb[256 + bcol] + bq2;
            g_Ux[base + (n0+3)*8] = a3 + hb[384 + bcol] + bq3;
        }
        __syncthreads();
    }

    // ================= Load quantized W row-tile, transposed, into SMEM (once) ====
    float* sWt = sm;            // [k][64 rows], stride 68
    float* sZ  = sm + 34816;    // [k][8 cols]  (4096)
    float* sRed= sm + 38912;    // 4 x 512 K-split partials
    float* sUx = sm + 40960;    // own 64x8 Ux tile
    {
        const int rb = mi * MROWS;
        for (int i = tid; i < MROWS*NDIM; i += TPB) {
            const int nl = i >> 9, k = i & 511;
            sWt[k*WSTRIDE + nl] = rintf(W[(rb + nl)*NDIM + k] / scW) * scW;
        }
    }
    sysbar(&g_gcnt, &g_ggen, GRID);
    if (cta == 0 && tid == 0) { g_maxW = 0u; g_maxU = 0u; g_maxB = 0u; } // reset for next replay

    // own Ux tile + first iteration z1 = relu(0.5*Ux)
    const int gout = nj*(NDIM*NBLK) + mi*(MROWS*NBLK);
    const int gblk = nj*(NDIM*NBLK);
    for (int i = tid; i < MROWS*NBLK; i += TPB) {
        const float v = __ldcg(&g_Ux[gout + i]);
        sUx[i] = v;
        g_zA[gout + i] = fmaxf(0.5f * v, 0.f);
    }
    float* gz_cur = g_zA;
    float* gz_nxt = g_zB;
    sysbar(&g_cnt[nj], &g_gen[nj], MT);

    // ================= Main loop: 39 remaining iterations =================
    const int ks = tid >> 6;               // K-split subgroup (k in [ks*128, ks*128+128))
    const int rr = tid & 63;
    const int bp = (rr & 3) << 1;          // 2 cols
    const int nb = (rr >> 2) << 2;         // 4 rows
    const float* wbase = sWt + ks*128*WSTRIDE + nb;
    const float* zsb   = sZ  + ks*128*8 + bp;
    const int outb = nb*8 + bp;

    for (int it = 0; it < ITERS - 1; ++it) {
        // stage this group's z block (512x8) into SMEM (L2-fresh)
        {
            const float4* src = (const float4*)(gz_cur + gblk);
            float4* dst = (float4*)sZ;
            #pragma unroll
            for (int i = 0; i < 4; ++i)
                dst[tid + i*TPB] = __ldcg(src + tid + i*TPB);
        }
        __syncthreads();

        float a00=0.f,a01=0.f,a10=0.f,a11=0.f,a20=0.f,a21=0.f,a30=0.f,a31=0.f;
        #pragma unroll 8
        for (int k = 0; k < 128; ++k) {
            const float4 w = *(const float4*)(wbase + k*WSTRIDE);
            const float2 z = *(const float2*)(zsb + k*8);
            a00 = fmaf(w.x, z.x, a00); a01 = fmaf(w.x, z.y, a01);
            a10 = fmaf(w.y, z.x, a10); a11 = fmaf(w.y, z.y, a11);
            a20 = fmaf(w.z, z.x, a20); a21 = fmaf(w.z, z.y, a21);
            a30 = fmaf(w.w, z.x, a30); a31 = fmaf(w.w, z.y, a31);
        }
        float* rp = sRed + ks*512 + outb;
        rp[0]  = a00; rp[1]  = a01; rp[8]  = a10; rp[9]  = a11;
        rp[16] = a20; rp[17] = a21; rp[24] = a30; rp[25] = a31;
        __syncthreads();

        #pragma unroll
        for (int o = 0; o < 2; ++o) {
            const int idx = tid + o*TPB;
            const float s = sRed[idx] + sRed[512+idx] + sRed[1024+idx] + sRed[1536+idx];
            const float zo = sZ[mi*(MROWS*NBLK) + idx];
            const float u = 0.5f*zo + 0.5f*(s + sUx[idx]);
            gz_nxt[gout + idx] = fmaxf(u, 0.f);
        }
        { float* t = gz_cur; gz_cur = gz_nxt; gz_nxt = t; }
        sysbar(&g_cnt[nj], &g_gen[nj], MT);
    }

    // ================= Classifier: logits[b][c] = z^T Wc^T + bc =================
    if (mi == 0 && tid < NBLK*CDIM) {
        const int bl = tid / CDIM;
        const int c  = tid - bl*CDIM;
        const float* zp = gz_cur + gblk + bl;
        const float* wc = Wc + c*NDIM;
        float acc = bcv[c];
        #pragma unroll 8
        for (int n = 0; n < NDIM; ++n)
            acc = fmaf(__ldcg(zp + n*8), wc[n], acc);
        out[(nj*NBLK + bl)*CDIM + c] = acc;
    }
}

extern "C" void kernel_launch(void* const* d_in, const int* in_sizes, int n_in,
                              void* d_out, int out_size) {
    (void)in_sizes; (void)n_in; (void)out_size;
    cudaFuncSetAttribute(mondeq_kernel, cudaFuncAttributeMaxDynamicSharedMemorySize, SMEM_BYTES);
    mondeq_kernel<<<GRID, TPB, SMEM_BYTES>>>(
        (const float*)d_in[0],   // W  (512,512)
        (const float*)d_in[1],   // U  (512,784)
        (const float*)d_in[2],   // b  (512)
        (const float*)d_in[3],   // x  (128,784)
        (const float*)d_in[4],   // Wc (10,512)
        (const float*)d_in[5],   // bc (10)
        (float*)d_out);          // logits (128,10)
}